// round 5
// baseline (speedup 1.0000x reference)
#include <cuda_runtime.h>
#include <math.h>

#define B_ 32
#define S_ 64
#define T_ 64
#define H_ 256
#define SOS 1
#define NBLK 128
#define NTHR 192

// ---------------- scratch (device globals: no allocation allowed) ----------------
__device__ float g_hT[2][H_ * B_];          // hidden state, transposed [j][b], double-buffered
__device__ float g_xT_all[S_ * H_ * B_];    // pre-gathered encoder inputs, [t][j][b]
__device__ float g_xT[H_ * B_];             // decoder x for current step, [j][b]
__device__ float g_EB[B_ * S_ * H_];        // encoder outputs, [b][s][j]
__device__ float g_c0[H_];                  // constant part of comb matmul (emb_sos term + bias)
__device__ float g_probs[B_ * T_];          // gathered probabilities
__device__ unsigned int g_bar_count = 0;
__device__ unsigned int g_bar_gen = 0;

__device__ __forceinline__ float wred(float v) {
#pragma unroll
    for (int o = 16; o > 0; o >>= 1) v += __shfl_xor_sync(0xffffffffu, v, o);
    return v;
}
__device__ __forceinline__ float wmax(float v) {
#pragma unroll
    for (int o = 16; o > 0; o >>= 1) v = fmaxf(v, __shfl_xor_sync(0xffffffffu, v, o));
    return v;
}

// Software grid barrier. Safe: 128 blocks x 192 threads, 1 block/SM, all resident.
__device__ __forceinline__ void grid_barrier() {
    __threadfence();      // make this thread's global writes visible (also flushes stale L1)
    __syncthreads();
    if (threadIdx.x == 0) {
        unsigned gen = *((volatile unsigned int*)&g_bar_gen);
        unsigned old = atomicAdd(&g_bar_count, 1u);
        if (old == NBLK - 1) {
            g_bar_count = 0;
            __threadfence();
            *((volatile unsigned int*)&g_bar_gen) = gen + 1u;
        } else {
            while (*((volatile unsigned int*)&g_bar_gen) == gen) { }
        }
    }
    __syncthreads();
}

__global__ void __launch_bounds__(NTHR, 1)
seq2seq_kernel(const int* __restrict__ ctx_tok, const int* __restrict__ inp_tok,
               const int* __restrict__ tsamp,
               const float* __restrict__ enc_emb,
               const float* __restrict__ enc_Wih, const float* __restrict__ enc_Whh,
               const float* __restrict__ enc_bih, const float* __restrict__ enc_bhh,
               const float* __restrict__ dec_emb,
               const float* __restrict__ W_comb, const float* __restrict__ b_comb,
               const float* __restrict__ dec_Wih, const float* __restrict__ dec_Whh,
               const float* __restrict__ dec_bih, const float* __restrict__ dec_bhh,
               const float* __restrict__ W_out, const float* __restrict__ b_out,
               float* __restrict__ out)
{
    extern __shared__ float sm[];
    float* sE   = sm;            // 16384: enc_outs for this block's b (blocks < 32)
    float* sh   = sm + 16384;    // 8192: staged hT
    float* sx   = sm + 24576;    // 8192: staged xT
    float* sgi  = sm + 32768;    // 192
    float* sgh  = sm + 32960;    // 192
    float* shb  = sm + 33152;    // 256: h[b][:] for attention
    float* satt = sm + 33408;    // 64:  scores / attn weights
    float* sctx = sm + 33472;    // 256
    float* sred = sm + 33728;    // 32

    const int tid  = threadIdx.x;
    const int lane = tid & 31;           // lane = b
    const int w    = tid >> 5;           // warp 0..5
    const int bx   = blockIdx.x;
    const int gate = w % 3;              // 0=r 1=z 2=n (PyTorch GRU chunk order)
    const int jl   = w / 3;
    const int j    = bx * 2 + jl;        // output hidden index 0..255
    const int k    = gate * H_ + j;      // gate-row index 0..767

    // ---------------- precompute (parallel) ----------------
    for (int i = bx * NTHR + tid; i < H_ * B_; i += NBLK * NTHR) g_hT[0][i] = 0.f;

    // gather encoder inputs: xT_all[t][jj][b] = enc_emb[context[b][t]][jj]
    for (int i = bx * NTHR + tid; i < S_ * B_ * H_; i += NBLK * NTHR) {
        int jj = i & (H_ - 1);
        int tb = i >> 8;
        int b  = tb & (B_ - 1);
        int t  = tb >> 5;
        int tok = ctx_tok[b * S_ + t];
        g_xT_all[(t * H_ + jj) * B_ + b] = enc_emb[(size_t)tok * H_ + jj];
    }
    // c0[j'] = b_comb[j'] + sum_jj W_comb[j', jj] * dec_emb[SOS][jj]
    {
        int gw = bx * 6 + w;
        if (gw < H_) {
            float s = 0.f;
#pragma unroll
            for (int m = 0; m < 8; m++) {
                int jj = lane + 32 * m;
                s += __ldg(&W_comb[(size_t)gw * (2 * H_) + jj]) * __ldg(&dec_emb[SOS * H_ + jj]);
            }
            s = wred(s);
            if (lane == 0) g_c0[gw] = s + b_comb[gw];
        }
    }
    grid_barrier();

    int buf = 0;

    const float4* wiE = (const float4*)(enc_Wih + (size_t)k * H_);
    const float4* whE = (const float4*)(enc_Whh + (size_t)k * H_);
    const float4* wiD = (const float4*)(dec_Wih + (size_t)k * H_);
    const float4* whD = (const float4*)(dec_Whh + (size_t)k * H_);
    const float biE = enc_bih[k], bhE = enc_bhh[k];
    const float biD = dec_bih[k], bhD = dec_bhh[k];

    // ---------------- encoder: 64 GRU steps, 1 barrier each ----------------
    for (int t = 0; t < S_; t++) {
        const float* hsrc = g_hT[buf];
        const float* xsrc = g_xT_all + t * H_ * B_;
        for (int i = tid; i < H_ * B_; i += NTHR) { sh[i] = __ldcg(hsrc + i); sx[i] = __ldcg(xsrc + i); }
        __syncthreads();

        float ai = biE, ah = bhE;
#pragma unroll 4
        for (int q = 0; q < H_ / 4; q++) {
            float4 a = __ldg(wiE + q);
            float4 c = __ldg(whE + q);
            int base = q * 4 * B_ + lane;
            ai += a.x * sx[base] + a.y * sx[base + B_] + a.z * sx[base + 2 * B_] + a.w * sx[base + 3 * B_];
            ah += c.x * sh[base] + c.y * sh[base + B_] + c.z * sh[base + 2 * B_] + c.w * sh[base + 3 * B_];
        }
        sgi[w * 32 + lane] = ai; sgh[w * 32 + lane] = ah;
        __syncthreads();
        if (gate == 0) {   // warps 0 and 3 combine their gate triple
            float r = 1.f / (1.f + expf(-(sgi[w * 32 + lane] + sgh[w * 32 + lane])));
            float z = 1.f / (1.f + expf(-(sgi[(w + 1) * 32 + lane] + sgh[(w + 1) * 32 + lane])));
            float n = tanhf(sgi[(w + 2) * 32 + lane] + r * sgh[(w + 2) * 32 + lane]);
            float hold = sh[j * B_ + lane];
            float hn = (1.f - z) * n + z * hold;
            g_hT[buf ^ 1][j * B_ + lane] = hn;
            g_EB[((size_t)lane * S_ + t) * H_ + j] = hn;
        }
        buf ^= 1;
        grid_barrier();
    }

    // ---------------- load this block's enc_outs into SMEM (persists through decode) ----------------
    if (bx < B_) {
        const float* esrc = g_EB + (size_t)bx * S_ * H_;
        for (int i = tid; i < S_ * H_; i += NTHR) sE[i] = __ldcg(esrc + i);
    }

    // ---------------- decoder: 64 steps, 2 barriers each ----------------
    for (int t = 0; t < T_; t++) {
        // ---- phase 1: gh dots (all blocks) + attention/x (blocks 0..31) ----
        const float* hsrc = g_hT[buf];
        for (int i = tid; i < H_ * B_; i += NTHR) sh[i] = __ldcg(hsrc + i);
        __syncthreads();

        float ah = bhD;
#pragma unroll 4
        for (int q = 0; q < H_ / 4; q++) {
            float4 c = __ldg(whD + q);
            int base = q * 4 * B_ + lane;
            ah += c.x * sh[base] + c.y * sh[base + B_] + c.z * sh[base + 2 * B_] + c.w * sh[base + 3 * B_];
        }

        if (bx < B_) {                       // this block owns batch element b = bx
            const int b = bx;
            for (int jj = tid; jj < H_; jj += NTHR) shb[jj] = sh[jj * B_ + b];
            __syncthreads();
            // scores[s] = enc_outs[s,b,:] . h[b,:]
            for (int s = w; s < S_; s += 6) {
                float p = 0.f;
#pragma unroll
                for (int m = 0; m < 8; m++) { int jj = lane + 32 * m; p += sE[s * H_ + jj] * shb[jj]; }
                p = wred(p);
                if (lane == 0) satt[s] = p;
            }
            __syncthreads();
            if (w == 0) {                    // softmax over 64 scores
                float v0 = satt[lane], v1 = satt[lane + 32];
                float mx = wmax(fmaxf(v0, v1));
                float e0 = expf(v0 - mx), e1 = expf(v1 - mx);
                float ssum = wred(e0 + e1);
                satt[lane] = e0 / ssum; satt[lane + 32] = e1 / ssum;
            }
            if (w == 1 && t > 0) {           // prob for previous step (uses h = h_new of step t-1)
                int tok = inp_tok[b * T_ + (t - 1)];
                float p = 0.f;
#pragma unroll
                for (int m = 0; m < 8; m++) { int jj = lane + 32 * m; p += shb[jj] * __ldg(&W_out[(size_t)tok * H_ + jj]); }
                p = wred(p);
                if (lane == 0) g_probs[b * T_ + (t - 1)] = 1.f / (1.f + expf(-(p + b_out[tok])));
            }
            __syncthreads();
            // ctx[jj] = sum_s attn[s] * enc_outs[s,b,jj]
            for (int jj = tid; jj < H_; jj += NTHR) {
                float c = 0.f;
                for (int s = 0; s < S_; s++) c += satt[s] * sE[s * H_ + jj];
                sctx[jj] = c;
            }
            __syncthreads();
            // x[j'] = relu(c0[j'] + W_comb[j', H:2H] . ctx)
            for (int jp = w; jp < H_; jp += 6) {
                const float* wr = W_comb + (size_t)jp * (2 * H_) + H_;
                float p = 0.f;
#pragma unroll
                for (int m = 0; m < 8; m++) { int jj = lane + 32 * m; p += __ldg(wr + jj) * sctx[jj]; }
                p = wred(p);
                if (lane == 0) {
                    float xv = g_c0[jp] + p;
                    g_xT[jp * B_ + b] = xv > 0.f ? xv : 0.f;
                }
            }
        }
        grid_barrier();

        // ---- phase 2: gi dots + GRU combine ----
        for (int i = tid; i < H_ * B_; i += NTHR) sx[i] = __ldcg(g_xT + i);
        __syncthreads();
        float ai = biD;
#pragma unroll 4
        for (int q = 0; q < H_ / 4; q++) {
            float4 a = __ldg(wiD + q);
            int base = q * 4 * B_ + lane;
            ai += a.x * sx[base] + a.y * sx[base + B_] + a.z * sx[base + 2 * B_] + a.w * sx[base + 3 * B_];
        }
        sgi[w * 32 + lane] = ai; sgh[w * 32 + lane] = ah;
        __syncthreads();
        if (gate == 0) {
            float r = 1.f / (1.f + expf(-(sgi[w * 32 + lane] + sgh[w * 32 + lane])));
            float z = 1.f / (1.f + expf(-(sgi[(w + 1) * 32 + lane] + sgh[(w + 1) * 32 + lane])));
            float n = tanhf(sgi[(w + 2) * 32 + lane] + r * sgh[(w + 2) * 32 + lane]);
            float hold = sh[j * B_ + lane];   // sh still holds h_{t} from phase 1
            float hn = (1.f - z) * n + z * hold;
            g_hT[buf ^ 1][j * B_ + lane] = hn;
        }
        buf ^= 1;
        grid_barrier();
    }

    // ---------------- final-step prob ----------------
    if (bx < B_) {
        const int b = bx;
        for (int jj = tid; jj < H_; jj += NTHR) shb[jj] = __ldcg(&g_hT[buf][jj * B_ + b]);
        __syncthreads();
        if (w == 0) {
            int tok = inp_tok[b * T_ + (T_ - 1)];
            float p = 0.f;
#pragma unroll
            for (int m = 0; m < 8; m++) { int jj = lane + 32 * m; p += shb[jj] * __ldg(&W_out[(size_t)tok * H_ + jj]); }
            p = wred(p);
            if (lane == 0) g_probs[b * T_ + (T_ - 1)] = 1.f / (1.f + expf(-(p + b_out[tok])));
        }
    }
    grid_barrier();

    // ---------------- outputs: out[0] = loss, out[1..] = probs [B,T] ----------------
    for (int i = bx * NTHR + tid; i < B_ * T_; i += NBLK * NTHR) out[1 + i] = __ldcg(g_probs + i);
    if (bx == 0) {
        float tv = tsamp ? (float)(*tsamp) : 1.0f;
        float acc = 0.f;
        for (int i = tid; i < B_ * T_; i += NTHR) {
            float p  = __ldcg(g_probs + i);
            float lp = fmaxf(logf(p), -100.f);
            float l1 = fmaxf(log1pf(-p), -100.f);
            acc += tv * lp + (1.f - tv) * l1;
        }
        acc = wred(acc);
        if (lane == 0) sred[w] = acc;
        __syncthreads();
        if (tid == 0) {
            float s = 0.f;
            for (int u = 0; u < 6; u++) s += sred[u];
            out[0] = -s / (float)(B_ * T_);
        }
    }
}

extern "C" void kernel_launch(void* const* d_in, const int* in_sizes, int n_in,
                              void* d_out, int out_size) {
    (void)in_sizes; (void)out_size;
    const size_t smem = 33760 * sizeof(float);   // 135040 B
    cudaFuncSetAttribute(seq2seq_kernel, cudaFuncAttributeMaxDynamicSharedMemorySize, (int)smem);

    // Defensive input indexing: true_sample may or may not be materialized as a tensor.
    int base = (n_in >= 17) ? 3 : 2;
    const int* ts = (n_in >= 17) ? (const int*)d_in[2] : nullptr;

    seq2seq_kernel<<<NBLK, NTHR, smem>>>(
        (const int*)d_in[0], (const int*)d_in[1], ts,
        (const float*)d_in[base + 0],  // enc_emb
        (const float*)d_in[base + 1],  // enc_Wih
        (const float*)d_in[base + 2],  // enc_Whh
        (const float*)d_in[base + 3],  // enc_bih
        (const float*)d_in[base + 4],  // enc_bhh
        (const float*)d_in[base + 5],  // dec_emb
        (const float*)d_in[base + 6],  // W_comb
        (const float*)d_in[base + 7],  // b_comb
        (const float*)d_in[base + 8],  // dec_Wih
        (const float*)d_in[base + 9],  // dec_Whh
        (const float*)d_in[base + 10], // dec_bih
        (const float*)d_in[base + 11], // dec_bhh
        (const float*)d_in[base + 12], // W_out
        (const float*)d_in[base + 13], // b_out
        (float*)d_out);
}

// round 6
// speedup vs baseline: 1.5012x; 1.5012x over previous
#include <cuda_runtime.h>
#include <math.h>

#define B_ 32
#define S_ 64
#define T_ 64
#define H_ 256
#define K3 768
#define SOS 1
#define NBLK 128
#define NTHR 192

// ---------------- device scratch ----------------
__device__ float g_hT[2][H_ * B_];          // hidden state [j][b], double-buffered
__device__ float g_xT_all[S_ * H_ * B_];    // encoder inputs [t][j][b]
__device__ float g_giE[S_ * K3 * B_];       // precomputed encoder gi [t][k][b]  (6 MB)
__device__ float g_xT[H_ * B_];             // decoder x [j'][b]
__device__ float g_EB[B_ * S_ * H_];        // encoder outputs [b][s][j]
__device__ float g_c0[H_];                  // constant half of comb matmul
__device__ float g_probs[B_ * T_];
__device__ __align__(128) unsigned int g_bar_count = 0;
__device__ __align__(128) unsigned int g_bar_gen = 0;

__device__ __forceinline__ float wred(float v) {
#pragma unroll
    for (int o = 16; o > 0; o >>= 1) v += __shfl_xor_sync(0xffffffffu, v, o);
    return v;
}
__device__ __forceinline__ float wmax(float v) {
#pragma unroll
    for (int o = 16; o > 0; o >>= 1) v = fmaxf(v, __shfl_xor_sync(0xffffffffu, v, o));
    return v;
}

// CG-style grid barrier: no per-thread fences, gpu-scope acquire/release only.
// Safe: 128 blocks, 1/SM, all resident.
__device__ __forceinline__ void grid_barrier() {
    __syncthreads();
    if (threadIdx.x == 0) {
        unsigned gen;
        asm volatile("ld.acquire.gpu.global.u32 %0, [%1];" : "=r"(gen) : "l"(&g_bar_gen));
        unsigned old;
        asm volatile("atom.release.gpu.global.add.u32 %0, [%1], %2;"
                     : "=r"(old) : "l"(&g_bar_count), "r"(1u) : "memory");
        if (old == NBLK - 1) {
            asm volatile("st.relaxed.gpu.global.u32 [%0], %1;" :: "l"(&g_bar_count), "r"(0u) : "memory");
            asm volatile("st.release.gpu.global.u32 [%0], %1;" :: "l"(&g_bar_gen), "r"(gen + 1u) : "memory");
        } else {
            unsigned cur;
            do {
                asm volatile("ld.acquire.gpu.global.u32 %0, [%1];" : "=r"(cur) : "l"(&g_bar_gen));
            } while (cur == gen);
        }
    }
    __syncthreads();
}

// stage 32KB [j][b] tile global->smem, vectorized
__device__ __forceinline__ void stage32KB(float* dst, const float* src, int tid) {
    const float4* s4 = (const float4*)src;
    float4* d4 = (float4*)dst;
    for (int i = tid; i < (H_ * B_) / 4; i += NTHR) d4[i] = __ldcg(s4 + i);
}

// dual-row dot: rows p0,p1 (256 floats each, float4) against sv[jj*32+lane]
__device__ __forceinline__ float2 dot2(const float4* __restrict__ p0, const float4* __restrict__ p1,
                                       const float* __restrict__ sv, int lane, float b0, float b1) {
    float a0a = b0, a0b = 0.f, a1a = b1, a1b = 0.f;
#pragma unroll 8
    for (int q = 0; q < 64; q++) {
        float4 wa = __ldg(p0 + q);
        float4 wb = __ldg(p1 + q);
        int base = q * 128 + lane;
        float h0 = sv[base], h1 = sv[base + 32], h2 = sv[base + 64], h3 = sv[base + 96];
        a0a += wa.x * h0; a0b += wa.y * h1; a0a += wa.z * h2; a0b += wa.w * h3;
        a1a += wb.x * h0; a1b += wb.y * h1; a1a += wb.z * h2; a1b += wb.w * h3;
    }
    return make_float2(a0a + a0b, a1a + a1b);
}

__global__ void __launch_bounds__(NTHR, 1)
seq2seq_kernel(const int* __restrict__ ctx_tok, const int* __restrict__ inp_tok,
               const int* __restrict__ tsamp,
               const float* __restrict__ enc_emb,
               const float* __restrict__ enc_Wih, const float* __restrict__ enc_Whh,
               const float* __restrict__ enc_bih, const float* __restrict__ enc_bhh,
               const float* __restrict__ dec_emb,
               const float* __restrict__ W_comb, const float* __restrict__ b_comb,
               const float* __restrict__ dec_Wih, const float* __restrict__ dec_Whh,
               const float* __restrict__ dec_bih, const float* __restrict__ dec_bhh,
               const float* __restrict__ W_out, const float* __restrict__ b_out,
               float* __restrict__ out)
{
    extern __shared__ float sm[];
    float* sE   = sm;             // 16384: enc_outs (attn blocks)
    float* sh   = sm + 16384;     // 8192: staged hT / x_t during precompute
    float* sx   = sm + 24576;     // 8192: staged xT (decoder phase 2)
    float* sgi  = sm + 32768;     // 384
    float* sgh  = sm + 33152;     // 384
    float* shb  = sm + 33536;     // 256
    float* satt = sm + 33792;     // 64
    float* sctx = sm + 33856;     // 256
    float* sred = sm + 34112;     // 32

    const int tid  = threadIdx.x;
    const int lane = tid & 31;       // lane = b in GRU dots
    const int w    = tid >> 5;       // warp 0..5
    const int bx   = blockIdx.x;

    // GRU row mapping (valid for bx < 64): 12 rows/block, 2 rows/warp
    const int gateW = w >> 1;
    const int pairW = w & 1;
    const int j0 = bx * 4 + pairW * 2;            // first j of this warp's pair
    const int lr0 = gateW * 4 + pairW * 2;        // local row idx (gate-major)
    const int lr1 = lr0 + 1;

    const float4 *whE0 = nullptr, *whE1 = nullptr, *whD0 = nullptr, *whD1 = nullptr,
                 *wiD0 = nullptr, *wiD1 = nullptr;
    float bhE0 = 0.f, bhE1 = 0.f, bhD0 = 0.f, bhD1 = 0.f, biD0 = 0.f, biD1 = 0.f;
    if (bx < 64) {
        const int k0 = gateW * H_ + j0, k1 = k0 + 1;
        whE0 = (const float4*)(enc_Whh + (size_t)k0 * H_);
        whE1 = (const float4*)(enc_Whh + (size_t)k1 * H_);
        whD0 = (const float4*)(dec_Whh + (size_t)k0 * H_);
        whD1 = (const float4*)(dec_Whh + (size_t)k1 * H_);
        wiD0 = (const float4*)(dec_Wih + (size_t)k0 * H_);
        wiD1 = (const float4*)(dec_Wih + (size_t)k1 * H_);
        bhE0 = enc_bhh[k0]; bhE1 = enc_bhh[k1];
        bhD0 = dec_bhh[k0]; bhD1 = dec_bhh[k1];
        biD0 = dec_bih[k0]; biD1 = dec_bih[k1];
    }

    // ---------------- init (parallel) ----------------
    for (int i = bx * NTHR + tid; i < H_ * B_; i += NBLK * NTHR) g_hT[0][i] = 0.f;

    for (int i = bx * NTHR + tid; i < S_ * B_ * H_; i += NBLK * NTHR) {
        int jj = i & (H_ - 1);
        int tb = i >> 8;
        int b  = tb & (B_ - 1);
        int t  = tb >> 5;
        int tok = ctx_tok[b * S_ + t];
        g_xT_all[(t * H_ + jj) * B_ + b] = enc_emb[(size_t)tok * H_ + jj];
    }
    {   // c0[j'] = b_comb[j'] + W_comb[j', 0:H] . dec_emb[SOS]
        int gw = bx * 6 + w;
        if (gw < H_) {
            float s = 0.f;
#pragma unroll
            for (int m = 0; m < 8; m++) {
                int jj = lane + 32 * m;
                s += __ldg(&W_comb[(size_t)gw * (2 * H_) + jj]) * __ldg(&dec_emb[SOS * H_ + jj]);
            }
            s = wred(s);
            if (lane == 0) g_c0[gw] = s + b_comb[gw];
        }
    }
    grid_barrier();

    // ---------------- encoder gi precompute (throughput-bound, parallel) ----------------
    {
        const int t  = bx >> 1;
        const int kh = (bx & 1) * 384;
        stage32KB(sh, g_xT_all + (size_t)t * H_ * B_, tid);
        __syncthreads();
        for (int i = 0; i < 32; i++) {
            int k0 = kh + w * 64 + 2 * i;
            int k1 = k0 + 1;
            const float4* pA = (const float4*)(enc_Wih + (size_t)k0 * H_);
            const float4* pB = (const float4*)(enc_Wih + (size_t)k1 * H_);
            float2 r = dot2(pA, pB, sh, lane, enc_bih[k0], enc_bih[k1]);
            g_giE[((size_t)t * K3 + k0) * B_ + lane] = r.x;
            g_giE[((size_t)t * K3 + k1) * B_ + lane] = r.y;
        }
    }
    grid_barrier();

    int buf = 0;

    // ---------------- encoder: 64 steps, 1 barrier each ----------------
    for (int t = 0; t < S_; t++) {
        if (bx < 64) {
            float gi0 = 0.f, gi1 = 0.f, gi2 = 0.f;
            if (w < 4) {   // prefetch gi for combine (independent of h)
                const float* gp = g_giE + ((size_t)t * K3 + (bx * 4 + w)) * B_ + lane;
                gi0 = __ldcg(gp);
                gi1 = __ldcg(gp + 256 * B_);
                gi2 = __ldcg(gp + 512 * B_);
            }
            stage32KB(sh, g_hT[buf], tid);
            __syncthreads();

            float2 gh = dot2(whE0, whE1, sh, lane, bhE0, bhE1);
            sgh[lr0 * 32 + lane] = gh.x;
            sgh[lr1 * 32 + lane] = gh.y;
            __syncthreads();

            if (w < 4) {
                int j = bx * 4 + w;
                float r = 1.f / (1.f + expf(-(gi0 + sgh[w * 32 + lane])));
                float z = 1.f / (1.f + expf(-(gi1 + sgh[(4 + w) * 32 + lane])));
                float n = tanhf(gi2 + r * sgh[(8 + w) * 32 + lane]);
                float hold = sh[j * B_ + lane];
                float hn = (1.f - z) * n + z * hold;
                g_hT[buf ^ 1][j * B_ + lane] = hn;
                g_EB[((size_t)lane * S_ + t) * H_ + j] = hn;
            }
        }
        buf ^= 1;
        grid_barrier();
        if (bx >= 64) {   // attn blocks: progressively stage enc_outs row t
            int b = (bx - 64) >> 1;
            const float4* src = (const float4*)(g_EB + ((size_t)b * S_ + t) * H_);
            float4* dst = (float4*)(sE + t * H_);
            if (tid < 64) dst[tid] = __ldcg(src + tid);
        }
    }

    // ---------------- decoder: 64 steps, 2 barriers each ----------------
    for (int t = 0; t < T_; t++) {
        // ---- phase 1 ----
        if (bx < 64) {
            stage32KB(sh, g_hT[buf], tid);
            __syncthreads();
            float2 gh = dot2(whD0, whD1, sh, lane, bhD0, bhD1);
            sgh[lr0 * 32 + lane] = gh.x;
            sgh[lr1 * 32 + lane] = gh.y;
        } else {
            const int bxa = bx - 64, b = bxa >> 1, half = bxa & 1;
            for (int jj = tid; jj < H_; jj += NTHR) shb[jj] = __ldcg(&g_hT[buf][jj * B_ + b]);
            __syncthreads();
            // scores[s] = enc_outs[s,b,:] . h[b,:]
            for (int s = w; s < S_; s += 6) {
                float p = 0.f;
#pragma unroll
                for (int m = 0; m < 8; m++) { int jj = lane + 32 * m; p += sE[s * H_ + jj] * shb[jj]; }
                p = wred(p);
                if (lane == 0) satt[s] = p;
            }
            __syncthreads();
            if (w == 0) {   // softmax over 64
                float v0 = satt[lane], v1 = satt[lane + 32];
                float mx = wmax(fmaxf(v0, v1));
                float e0 = expf(v0 - mx), e1 = expf(v1 - mx);
                float ssum = wred(e0 + e1);
                satt[lane] = e0 / ssum; satt[lane + 32] = e1 / ssum;
            }
            if (w == 1 && half == 1 && t > 0) {   // prob for step t-1
                int tok = inp_tok[b * T_ + (t - 1)];
                float p = 0.f;
#pragma unroll
                for (int m = 0; m < 8; m++) { int jj = lane + 32 * m; p += shb[jj] * __ldg(&W_out[(size_t)tok * H_ + jj]); }
                p = wred(p);
                if (lane == 0) g_probs[b * T_ + (t - 1)] = 1.f / (1.f + expf(-(p + b_out[tok])));
            }
            __syncthreads();
            // ctx
            for (int jj = tid; jj < H_; jj += NTHR) {
                float c = 0.f;
                for (int s = 0; s < S_; s++) c += satt[s] * sE[s * H_ + jj];
                sctx[jj] = c;
            }
            __syncthreads();
            // x half: jp in [half*128, half*128+128)
            for (int jp = half * 128 + w; jp < half * 128 + 128; jp += 6) {
                const float* wr = W_comb + (size_t)jp * (2 * H_) + H_;
                float p = 0.f;
#pragma unroll
                for (int m = 0; m < 8; m++) { int jj = lane + 32 * m; p += __ldg(wr + jj) * sctx[jj]; }
                p = wred(p);
                if (lane == 0) {
                    float xv = g_c0[jp] + p;
                    g_xT[jp * B_ + b] = xv > 0.f ? xv : 0.f;
                }
            }
        }
        grid_barrier();

        // ---- phase 2 ----
        if (bx < 64) {
            stage32KB(sx, g_xT, tid);
            __syncthreads();
            float2 gi = dot2(wiD0, wiD1, sx, lane, biD0, biD1);
            sgi[lr0 * 32 + lane] = gi.x;
            sgi[lr1 * 32 + lane] = gi.y;
            __syncthreads();
            if (w < 4) {
                int j = bx * 4 + w;
                float r = 1.f / (1.f + expf(-(sgi[w * 32 + lane] + sgh[w * 32 + lane])));
                float z = 1.f / (1.f + expf(-(sgi[(4 + w) * 32 + lane] + sgh[(4 + w) * 32 + lane])));
                float n = tanhf(sgi[(8 + w) * 32 + lane] + r * sgh[(8 + w) * 32 + lane]);
                float hold = sh[j * B_ + lane];   // sh untouched since phase 1
                float hn = (1.f - z) * n + z * hold;
                g_hT[buf ^ 1][j * B_ + lane] = hn;
            }
        }
        buf ^= 1;
        grid_barrier();
    }

    // ---------------- final-step prob ----------------
    if (bx >= 64 && ((bx - 64) & 1) == 1) {
        const int b = (bx - 64) >> 1;
        for (int jj = tid; jj < H_; jj += NTHR) shb[jj] = __ldcg(&g_hT[buf][jj * B_ + b]);
        __syncthreads();
        if (w == 0) {
            int tok = inp_tok[b * T_ + (T_ - 1)];
            float p = 0.f;
#pragma unroll
            for (int m = 0; m < 8; m++) { int jj = lane + 32 * m; p += shb[jj] * __ldg(&W_out[(size_t)tok * H_ + jj]); }
            p = wred(p);
            if (lane == 0) g_probs[b * T_ + (T_ - 1)] = 1.f / (1.f + expf(-(p + b_out[tok])));
        }
    }
    grid_barrier();

    // ---------------- outputs ----------------
    for (int i = bx * NTHR + tid; i < B_ * T_; i += NBLK * NTHR) out[1 + i] = __ldcg(g_probs + i);
    if (bx == 0) {
        float tv = tsamp ? (float)(*tsamp) : 1.0f;
        float acc = 0.f;
        for (int i = tid; i < B_ * T_; i += NTHR) {
            float p  = __ldcg(g_probs + i);
            float lp = fmaxf(logf(p), -100.f);
            float l1 = fmaxf(log1pf(-p), -100.f);
            acc += tv * lp + (1.f - tv) * l1;
        }
        acc = wred(acc);
        if (lane == 0) sred[w] = acc;
        __syncthreads();
        if (tid == 0) {
            float s = 0.f;
            for (int u = 0; u < 6; u++) s += sred[u];
            out[0] = -s / (float)(B_ * T_);
        }
    }
}

extern "C" void kernel_launch(void* const* d_in, const int* in_sizes, int n_in,
                              void* d_out, int out_size) {
    (void)in_sizes; (void)out_size;
    const size_t smem = 34144 * sizeof(float);   // 136576 B
    cudaFuncSetAttribute(seq2seq_kernel, cudaFuncAttributeMaxDynamicSharedMemorySize, (int)smem);

    int base = (n_in >= 17) ? 3 : 2;
    const int* ts = (n_in >= 17) ? (const int*)d_in[2] : nullptr;

    seq2seq_kernel<<<NBLK, NTHR, smem>>>(
        (const int*)d_in[0], (const int*)d_in[1], ts,
        (const float*)d_in[base + 0],  // enc_emb
        (const float*)d_in[base + 1],  // enc_Wih
        (const float*)d_in[base + 2],  // enc_Whh
        (const float*)d_in[base + 3],  // enc_bih
        (const float*)d_in[base + 4],  // enc_bhh
        (const float*)d_in[base + 5],  // dec_emb
        (const float*)d_in[base + 6],  // W_comb
        (const float*)d_in[base + 7],  // b_comb
        (const float*)d_in[base + 8],  // dec_Wih
        (const float*)d_in[base + 9],  // dec_Whh
        (const float*)d_in[base + 10], // dec_bih
        (const float*)d_in[base + 11], // dec_bhh
        (const float*)d_in[base + 12], // W_out
        (const float*)d_in[base + 13], // b_out
        (float*)d_out);
}

// round 7
// speedup vs baseline: 2.0827x; 1.3873x over previous
#include <cuda_runtime.h>
#include <math.h>

#define B_ 32
#define S_ 64
#define T_ 64
#define H_ 256
#define K3 768
#define SOS 1
#define NBLK 128
#define NTHR 192

// ---------------- device scratch ----------------
__device__ float g_hT[2][H_ * B_];          // hidden state [j][b], double-buffered
__device__ float g_hB[B_ * H_];             // hidden state row-major [b][j] (for attn staging)
__device__ float g_xT_all[S_ * H_ * B_];    // encoder inputs [t][j][b]
__device__ float g_giE[S_ * K3 * B_];       // precomputed encoder gi [t][k][b]
__device__ float g_xT[H_ * B_];             // decoder x [j'][b]
__device__ float g_ctx[H_ * B_];            // attention context [jj][b]
__device__ float g_EB[B_ * S_ * H_];        // encoder outputs [b][s][j]
__device__ float g_c0[H_];                  // constant half of comb matmul
__device__ float g_probs[B_ * T_];
__device__ __align__(128) unsigned int g_bar_count = 0;   // legacy gen barrier (self-cleaning)
__device__ __align__(128) unsigned int g_bar_gen = 0;
__device__ __align__(128) unsigned int g_bar2 = 0;        // monotone barrier counter
__device__ __align__(128) unsigned int g_ctxc = 0;        // ctx-ready flag (monotone)
__device__ __align__(128) unsigned int g_xc = 0;          // x-ready flag (monotone)

__device__ __forceinline__ float wred(float v) {
#pragma unroll
    for (int o = 16; o > 0; o >>= 1) v += __shfl_xor_sync(0xffffffffu, v, o);
    return v;
}
__device__ __forceinline__ float wmax(float v) {
#pragma unroll
    for (int o = 16; o > 0; o >>= 1) v = fmaxf(v, __shfl_xor_sync(0xffffffffu, v, o));
    return v;
}

__device__ __forceinline__ void red_add_release(unsigned int* p) {
    asm volatile("red.release.gpu.global.add.u32 [%0], 1;" :: "l"(p) : "memory");
}
__device__ __forceinline__ unsigned int ld_acq(unsigned int* p) {
    unsigned int v;
    asm volatile("ld.acquire.gpu.global.u32 %0, [%1];" : "=r"(v) : "l"(p));
    return v;
}
__device__ __forceinline__ void spin_ge(unsigned int* p, unsigned int target) {
    while ((int)(ld_acq(p) - target) < 0) { }
}
__device__ __forceinline__ void spin_ge_backoff(unsigned int* p, unsigned int target) {
    int it = 0;
    while ((int)(ld_acq(p) - target) < 0) { if (++it > 8) __nanosleep(64); }
}

// legacy self-cleaning barrier (used only for the two init syncs; safe across graph replays)
__device__ __forceinline__ void gen_barrier() {
    __syncthreads();
    if (threadIdx.x == 0) {
        unsigned gen;
        asm volatile("ld.acquire.gpu.global.u32 %0, [%1];" : "=r"(gen) : "l"(&g_bar_gen));
        unsigned old;
        asm volatile("atom.release.gpu.global.add.u32 %0, [%1], %2;"
                     : "=r"(old) : "l"(&g_bar_count), "r"(1u) : "memory");
        if (old == NBLK - 1) {
            asm volatile("st.relaxed.gpu.global.u32 [%0], %1;" :: "l"(&g_bar_count), "r"(0u) : "memory");
            asm volatile("st.release.gpu.global.u32 [%0], %1;" :: "l"(&g_bar_gen), "r"(gen + 1u) : "memory");
        } else {
            unsigned cur;
            do { asm volatile("ld.acquire.gpu.global.u32 %0, [%1];" : "=r"(cur) : "l"(&g_bar_gen)); }
            while (cur == gen);
        }
    }
    __syncthreads();
}

// monotone REDG barrier: no releaser round trip
__device__ __forceinline__ void red_barrier(unsigned int target) {
    __syncthreads();
    if (threadIdx.x == 0) {
        red_add_release(&g_bar2);
        spin_ge_backoff(&g_bar2, target);
    }
    __syncthreads();
}

// stage 32KB [j][b] tile global->smem, vectorized
__device__ __forceinline__ void stage32KB(float* dst, const float* src, int tid) {
    const float4* s4 = (const float4*)src;
    float4* d4 = (float4*)dst;
    for (int i = tid; i < (H_ * B_) / 4; i += NTHR) d4[i] = __ldcg(s4 + i);
}

// dual-row dot: rows p0,p1 against sv[jj*32+lane]
__device__ __forceinline__ float2 dot2(const float4* __restrict__ p0, const float4* __restrict__ p1,
                                       const float* __restrict__ sv, int lane, float b0, float b1) {
    float a0a = b0, a0b = 0.f, a1a = b1, a1b = 0.f;
#pragma unroll 8
    for (int q = 0; q < 64; q++) {
        float4 wa = __ldg(p0 + q);
        float4 wb = __ldg(p1 + q);
        int base = q * 128 + lane;
        float h0 = sv[base], h1 = sv[base + 32], h2 = sv[base + 64], h3 = sv[base + 96];
        a0a += wa.x * h0; a0b += wa.y * h1; a0a += wa.z * h2; a0b += wa.w * h3;
        a1a += wb.x * h0; a1b += wb.y * h1; a1a += wb.z * h2; a1b += wb.w * h3;
    }
    return make_float2(a0a + a0b, a1a + a1b);
}

// single-row dot
__device__ __forceinline__ float dot1(const float4* __restrict__ p0,
                                      const float* __restrict__ sv, int lane, float b0) {
    float a0 = b0, a1 = 0.f;
#pragma unroll 8
    for (int q = 0; q < 64; q++) {
        float4 wa = __ldg(p0 + q);
        int base = q * 128 + lane;
        a0 += wa.x * sv[base];      a1 += wa.y * sv[base + 32];
        a0 += wa.z * sv[base + 64]; a1 += wa.w * sv[base + 96];
    }
    return a0 + a1;
}

__global__ void __launch_bounds__(NTHR, 1)
seq2seq_kernel(const int* __restrict__ ctx_tok, const int* __restrict__ inp_tok,
               const int* __restrict__ tsamp,
               const float* __restrict__ enc_emb,
               const float* __restrict__ enc_Wih, const float* __restrict__ enc_Whh,
               const float* __restrict__ enc_bih, const float* __restrict__ enc_bhh,
               const float* __restrict__ dec_emb,
               const float* __restrict__ W_comb, const float* __restrict__ b_comb,
               const float* __restrict__ dec_Wih, const float* __restrict__ dec_Whh,
               const float* __restrict__ dec_bih, const float* __restrict__ dec_bhh,
               const float* __restrict__ W_out, const float* __restrict__ b_out,
               float* __restrict__ out)
{
    extern __shared__ float sm[];
    float* sE   = sm;             // 16384: enc_outs (attn blocks)
    float* sh   = sm + 16384;     // 8192: staged hT
    float* sx   = sm + 24576;     // 8192: staged ctx / x
    float* sgi  = sm + 32768;     // 384
    float* sgh  = sm + 33152;     // 384
    float* shb  = sm + 33536;     // 256
    float* satt = sm + 33792;     // 64
    float* sred = sm + 33856;     // 32

    const int tid  = threadIdx.x;
    const int lane = tid & 31;       // lane = b in GRU dots
    const int w    = tid >> 5;       // warp 0..5
    const int bx   = blockIdx.x;

    unsigned ep = 0;                 // barrier epoch (monotone)

    // ---- encoder row mapping (all 128 blocks, 6 rows each, 1 row/warp) ----
    const int gE = w >> 1;                    // gate 0..2
    const int pE = w & 1;
    const int jE = bx * 2 + pE;               // row j (0..255)
    const int kE = gE * H_ + jE;

    // ---- decoder GRU mapping (bx < 64): 12 rows/block, 2 rows/warp ----
    const int gateW = w >> 1;
    const int pairW = w & 1;
    const int j0 = bx * 4 + pairW * 2;
    const int lr0 = gateW * 4 + pairW * 2;
    const int lr1 = lr0 + 1;

    const float4* whE = (const float4*)(enc_Whh + (size_t)kE * H_);
    const float bhE = enc_bhh[kE];

    const float4 *whD0 = nullptr, *whD1 = nullptr, *wiD0 = nullptr, *wiD1 = nullptr;
    float bhD0 = 0.f, bhD1 = 0.f, biD0 = 0.f, biD1 = 0.f;
    if (bx < 64) {
        const int k0 = gateW * H_ + j0, k1 = k0 + 1;
        whD0 = (const float4*)(dec_Whh + (size_t)k0 * H_);
        whD1 = (const float4*)(dec_Whh + (size_t)k1 * H_);
        wiD0 = (const float4*)(dec_Wih + (size_t)k0 * H_);
        wiD1 = (const float4*)(dec_Wih + (size_t)k1 * H_);
        bhD0 = dec_bhh[k0]; bhD1 = dec_bhh[k1];
        biD0 = dec_bih[k0]; biD1 = dec_bih[k1];
    }

    // ---------------- init (parallel) ----------------
    if (bx == 0 && tid == 0) { g_bar2 = 0u; g_ctxc = 0u; g_xc = 0u; }

    for (int i = bx * NTHR + tid; i < H_ * B_; i += NBLK * NTHR) g_hT[0][i] = 0.f;

    for (int i = bx * NTHR + tid; i < S_ * B_ * H_; i += NBLK * NTHR) {
        int jj = i & (H_ - 1);
        int tb = i >> 8;
        int b  = tb & (B_ - 1);
        int t  = tb >> 5;
        int tok = ctx_tok[b * S_ + t];
        g_xT_all[(t * H_ + jj) * B_ + b] = enc_emb[(size_t)tok * H_ + jj];
    }
    {   // c0[j'] = b_comb[j'] + W_comb[j', 0:H] . dec_emb[SOS]
        int gw = bx * 6 + w;
        if (gw < H_) {
            float s = 0.f;
#pragma unroll
            for (int m = 0; m < 8; m++) {
                int jj = lane + 32 * m;
                s += __ldg(&W_comb[(size_t)gw * (2 * H_) + jj]) * __ldg(&dec_emb[SOS * H_ + jj]);
            }
            s = wred(s);
            if (lane == 0) g_c0[gw] = s + b_comb[gw];
        }
    }
    gen_barrier();

    // ---------------- encoder gi precompute (parallel) ----------------
    {
        const int t  = bx >> 1;
        const int kh = (bx & 1) * 384;
        stage32KB(sh, g_xT_all + (size_t)t * H_ * B_, tid);
        __syncthreads();
        for (int i = 0; i < 32; i++) {
            int k0 = kh + w * 64 + 2 * i;
            int k1 = k0 + 1;
            const float4* pA = (const float4*)(enc_Wih + (size_t)k0 * H_);
            const float4* pB = (const float4*)(enc_Wih + (size_t)k1 * H_);
            float2 r = dot2(pA, pB, sh, lane, enc_bih[k0], enc_bih[k1]);
            g_giE[((size_t)t * K3 + k0) * B_ + lane] = r.x;
            g_giE[((size_t)t * K3 + k1) * B_ + lane] = r.y;
        }
    }
    gen_barrier();

    int buf = 0;

    // ---------------- encoder: 64 steps, 1 red-barrier each, all 128 blocks ----------------
    for (int t = 0; t < S_; t++) {
        float gi0 = 0.f, gi1 = 0.f, gi2 = 0.f;
        if (w < 2) {   // prefetch gi for combine rows j = bx*2 + w
            const float* gp = g_giE + ((size_t)t * K3 + (bx * 2 + w)) * B_ + lane;
            gi0 = __ldcg(gp);
            gi1 = __ldcg(gp + 256 * B_);
            gi2 = __ldcg(gp + 512 * B_);
        }
        stage32KB(sh, g_hT[buf], tid);
        __syncthreads();

        sgh[w * 32 + lane] = dot1(whE, sh, lane, bhE);
        __syncthreads();

        if (w < 2) {
            int j = bx * 2 + w;
            float r = 1.f / (1.f + expf(-(gi0 + sgh[w * 32 + lane])));
            float z = 1.f / (1.f + expf(-(gi1 + sgh[(2 + w) * 32 + lane])));
            float n = tanhf(gi2 + r * sgh[(4 + w) * 32 + lane]);
            float hold = sh[j * B_ + lane];
            float hn = (1.f - z) * n + z * hold;
            g_hT[buf ^ 1][j * B_ + lane] = hn;
            g_EB[((size_t)lane * S_ + t) * H_ + j] = hn;
            g_hB[lane * H_ + j] = hn;
        }
        buf ^= 1;
        ep += NBLK; red_barrier(ep);
        if (bx >= 64) {   // attn blocks progressively stage enc_outs row t
            int b = (bx - 64) >> 1;
            const float4* src = (const float4*)(g_EB + ((size_t)b * S_ + t) * H_);
            float4* dst = (float4*)(sE + t * H_);
            if (tid < 64) dst[tid] = __ldcg(src + tid);
        }
    }

    // ---------------- decoder: 64 steps, 1 red-barrier + 2 flags each ----------------
    for (int t = 0; t < T_; t++) {
        if (bx < 64) {
            // ---- GRU block path ----
            stage32KB(sh, g_hT[buf], tid);
            __syncthreads();
            float2 gh = dot2(whD0, whD1, sh, lane, bhD0, bhD1);
            sgh[lr0 * 32 + lane] = gh.x;
            sgh[lr1 * 32 + lane] = gh.y;
            // wait for ctx from attn blocks
            if (tid == 0) spin_ge(&g_ctxc, (unsigned)(64 * (t + 1)));
            __syncthreads();
            stage32KB(sx, g_ctx, tid);
            __syncthreads();
            if (w < 4) {          // x rows jp = bx*4 + w  (W_comb2 rows: 4KB/block, L1-resident)
                int jp = bx * 4 + w;
                const float4* wc = (const float4*)(W_comb + (size_t)jp * (2 * H_) + H_);
                float xv = dot1(wc, sx, lane, g_c0[jp]);
                g_xT[jp * B_ + lane] = xv > 0.f ? xv : 0.f;
            }
            __syncthreads();
            if (tid == 0) {
                red_add_release(&g_xc);
                spin_ge(&g_xc, (unsigned)(64 * (t + 1)));
            }
            __syncthreads();
            stage32KB(sx, g_xT, tid);
            __syncthreads();
            float2 gi = dot2(wiD0, wiD1, sx, lane, biD0, biD1);
            sgi[lr0 * 32 + lane] = gi.x;
            sgi[lr1 * 32 + lane] = gi.y;
            __syncthreads();
            if (w < 4) {
                int j = bx * 4 + w;
                float r = 1.f / (1.f + expf(-(sgi[w * 32 + lane] + sgh[w * 32 + lane])));
                float z = 1.f / (1.f + expf(-(sgi[(4 + w) * 32 + lane] + sgh[(4 + w) * 32 + lane])));
                float n = tanhf(sgi[(8 + w) * 32 + lane] + r * sgh[(8 + w) * 32 + lane]);
                float hold = sh[j * B_ + lane];
                float hn = (1.f - z) * n + z * hold;
                g_hT[buf ^ 1][j * B_ + lane] = hn;
                g_hB[lane * H_ + j] = hn;
            }
        } else {
            // ---- attention block path: b = (bx-64)>>1, half = (bx-64)&1 ----
            const int bxa = bx - 64, b = bxa >> 1, half = bxa & 1;
            if (tid < 64) ((float4*)shb)[tid] = __ldcg(((const float4*)(g_hB + b * H_)) + tid);
            __syncthreads();
            // scores[s] = enc_outs[s,b,:] . h[b,:]
            for (int s = w; s < S_; s += 6) {
                float p = 0.f;
#pragma unroll
                for (int m = 0; m < 8; m++) { int jj = lane + 32 * m; p += sE[s * H_ + jj] * shb[jj]; }
                p = wred(p);
                if (lane == 0) satt[s] = p;
            }
            __syncthreads();
            if (w == 0) {   // softmax over 64
                float v0 = satt[lane], v1 = satt[lane + 32];
                float mx = wmax(fmaxf(v0, v1));
                float e0 = expf(v0 - mx), e1 = expf(v1 - mx);
                float ssum = wred(e0 + e1);
                satt[lane] = e0 / ssum; satt[lane + 32] = e1 / ssum;
            }
            if (w == 1 && half == 1 && t > 0) {   // prob for step t-1 (h here = h_new of t-1)
                int tok = inp_tok[b * T_ + (t - 1)];
                float p = 0.f;
#pragma unroll
                for (int m = 0; m < 8; m++) { int jj = lane + 32 * m; p += shb[jj] * __ldg(&W_out[(size_t)tok * H_ + jj]); }
                p = wred(p);
                if (lane == 0) g_probs[b * T_ + (t - 1)] = 1.f / (1.f + expf(-(p + b_out[tok])));
            }
            __syncthreads();
            // ctx half: jj in [half*128, half*128+128) -> g_ctx[jj][b]
            if (tid < 128) {
                int jj = half * 128 + tid;
                float c = 0.f;
#pragma unroll 8
                for (int s = 0; s < S_; s++) c += satt[s] * sE[s * H_ + jj];
                g_ctx[jj * B_ + b] = c;
            }
            __syncthreads();
            if (tid == 0) red_add_release(&g_ctxc);
        }
        buf ^= 1;
        ep += NBLK; red_barrier(ep);
    }

    // ---------------- final-step prob ----------------
    if (bx >= 64 && ((bx - 64) & 1) == 1) {
        const int b = (bx - 64) >> 1;
        if (tid < 64) ((float4*)shb)[tid] = __ldcg(((const float4*)(g_hB + b * H_)) + tid);
        __syncthreads();
        if (w == 0) {
            int tok = inp_tok[b * T_ + (T_ - 1)];
            float p = 0.f;
#pragma unroll
            for (int m = 0; m < 8; m++) { int jj = lane + 32 * m; p += shb[jj] * __ldg(&W_out[(size_t)tok * H_ + jj]); }
            p = wred(p);
            if (lane == 0) g_probs[b * T_ + (T_ - 1)] = 1.f / (1.f + expf(-(p + b_out[tok])));
        }
    }
    ep += NBLK; red_barrier(ep);

    // ---------------- outputs ----------------
    for (int i = bx * NTHR + tid; i < B_ * T_; i += NBLK * NTHR) out[1 + i] = __ldcg(g_probs + i);
    if (bx == 0) {
        float tv = tsamp ? (float)(*tsamp) : 1.0f;
        float acc = 0.f;
        for (int i = tid; i < B_ * T_; i += NTHR) {
            float p  = __ldcg(g_probs + i);
            float lp = fmaxf(logf(p), -100.f);
            float l1 = fmaxf(log1pf(-p), -100.f);
            acc += tv * lp + (1.f - tv) * l1;
        }
        acc = wred(acc);
        if (lane == 0) sred[w] = acc;
        __syncthreads();
        if (tid == 0) {
            float s = 0.f;
            for (int u = 0; u < 6; u++) s += sred[u];
            out[0] = -s / (float)(B_ * T_);
        }
    }
}

extern "C" void kernel_launch(void* const* d_in, const int* in_sizes, int n_in,
                              void* d_out, int out_size) {
    (void)in_sizes; (void)out_size;
    const size_t smem = 33888 * sizeof(float);   // 135552 B
    cudaFuncSetAttribute(seq2seq_kernel, cudaFuncAttributeMaxDynamicSharedMemorySize, (int)smem);

    int base = (n_in >= 17) ? 3 : 2;
    const int* ts = (n_in >= 17) ? (const int*)d_in[2] : nullptr;

    seq2seq_kernel<<<NBLK, NTHR, smem>>>(
        (const int*)d_in[0], (const int*)d_in[1], ts,
        (const float*)d_in[base + 0],  // enc_emb
        (const float*)d_in[base + 1],  // enc_Wih
        (const float*)d_in[base + 2],  // enc_Whh
        (const float*)d_in[base + 3],  // enc_bih
        (const float*)d_in[base + 4],  // enc_bhh
        (const float*)d_in[base + 5],  // dec_emb
        (const float*)d_in[base + 6],  // W_comb
        (const float*)d_in[base + 7],  // b_comb
        (const float*)d_in[base + 8],  // dec_Wih
        (const float*)d_in[base + 9],  // dec_Whh
        (const float*)d_in[base + 10], // dec_bih
        (const float*)d_in[base + 11], // dec_bhh
        (const float*)d_in[base + 12], // W_out
        (const float*)d_in[base + 13], // b_out
        (float*)d_out);
}